// round 8
// baseline (speedup 1.0000x reference)
#include <cuda_runtime.h>

#define N_NODES   50000
#define MAX_EDGES 600000
#define DIM       128
#define N_CLASSES 40
#define N_GRAPHS  128

// ---------------- static device scratch (16B-aligned: float4 traffic) ---------
__device__ __align__(16) float g_agg[N_NODES * DIM];
__device__ __align__(16) float g_h1[N_NODES * DIM];
__device__ __align__(16) float g_h2[N_NODES * DIM];
__device__ int   g_deg[N_NODES];
__device__ int   g_rowoff[N_NODES + 1];
__device__ int   g_cursor[N_NODES];
__device__ int   g_csrsrc[MAX_EDGES];
__device__ float g_invcnt[N_NODES];
__device__ float g_gsum[N_GRAPHS * N_CLASSES];
__device__ float g_gcnt[N_GRAPHS];

// device-side buffer selector: 0 = external ptr (param), 1 = g_h1, 2 = g_h2
__device__ __forceinline__ const float* pick_in(int w, const float* x) {
    if (w == 1) return g_h1;
    if (w == 2) return g_h2;
    return x;
}
__device__ __forceinline__ float* pick_out(int w, float* dout) {
    if (w == 1) return g_h1;
    if (w == 2) return g_h2;
    return dout;
}

// ---------------- zero per-call scratch ----------------
__global__ void k_zero() {
    int i = blockIdx.x * blockDim.x + threadIdx.x;
    if (i < N_NODES) g_deg[i] = 0;
    if (i < N_GRAPHS * N_CLASSES) g_gsum[i] = 0.f;
    if (i < N_GRAPHS) g_gcnt[i] = 0.f;
}

// ---------------- degree count (edge_index is INT32: jax x64 is disabled) ----
__global__ void k_count(const int* __restrict__ ei, int E) {
    int e = blockIdx.x * blockDim.x + threadIdx.x;
    if (e < E) {
        int d = ei[E + e];
        if ((unsigned)d < (unsigned)N_NODES) atomicAdd(&g_deg[d], 1);
    }
}

// ---------------- single-block exclusive scan over degrees ----------------
__global__ void k_scan(int E) {
    __shared__ int sums[1024];
    const int tid = threadIdx.x;
    const int CH = (N_NODES + 1023) / 1024;  // 49
    const int base = tid * CH;
    int s = 0;
    for (int i = 0; i < CH; i++) {
        int idx = base + i;
        if (idx < N_NODES) s += g_deg[idx];
    }
    sums[tid] = s;
    __syncthreads();
    for (int off = 1; off < 1024; off <<= 1) {
        int v = 0;
        if (tid >= off) v = sums[tid - off];
        __syncthreads();
        sums[tid] += v;
        __syncthreads();
    }
    int run = (tid == 0) ? 0 : sums[tid - 1];
    for (int i = 0; i < CH; i++) {
        int idx = base + i;
        if (idx < N_NODES) {
            g_rowoff[idx] = run;
            g_cursor[idx] = run;
            int d = g_deg[idx];
            run += d;
            g_invcnt[idx] = 1.0f / (float)max(d, 1);
        }
    }
    if (tid == 0) g_rowoff[N_NODES] = E;
}

// ---------------- fill CSR (src lists grouped by dst) ----------------
__global__ void k_fill(const int* __restrict__ ei, int E) {
    int e = blockIdx.x * blockDim.x + threadIdx.x;
    if (e < E) {
        int s = ei[e];
        int d = ei[E + e];
        if ((unsigned)s < (unsigned)N_NODES && (unsigned)d < (unsigned)N_NODES) {
            int p = atomicAdd(&g_cursor[d], 1);
            g_csrsrc[p] = s;
        }
    }
}

// ---------------- aggregation: g_agg[n] = mean over in-edges of relu(h[src]) --
// one warp per node; lane owns one float4. h tensors L2-resident (25.6 MB).
__global__ void k_agg(const float* __restrict__ xext, int which_in) {
    const float4* hin = (const float4*)pick_in(which_in, xext);
    float4* agg = (float4*)g_agg;
    const int* __restrict__ rowoff = g_rowoff;
    const int* __restrict__ csrsrc = g_csrsrc;
    int w = (blockIdx.x * blockDim.x + threadIdx.x) >> 5;
    int lane = threadIdx.x & 31;
    if (w >= N_NODES) return;
    int beg = rowoff[w];
    int end = rowoff[w + 1];
    float4 acc = make_float4(0.f, 0.f, 0.f, 0.f);
    int e = beg;
    for (; e + 1 < end; e += 2) {
        int s0 = csrsrc[e];
        int s1 = csrsrc[e + 1];
        float4 v0 = hin[s0 * 32 + lane];
        float4 v1 = hin[s1 * 32 + lane];
        acc.x += fmaxf(v0.x, 0.f) + fmaxf(v1.x, 0.f);
        acc.y += fmaxf(v0.y, 0.f) + fmaxf(v1.y, 0.f);
        acc.z += fmaxf(v0.z, 0.f) + fmaxf(v1.z, 0.f);
        acc.w += fmaxf(v0.w, 0.f) + fmaxf(v1.w, 0.f);
    }
    if (e < end) {
        int s0 = csrsrc[e];
        float4 v0 = hin[s0 * 32 + lane];
        acc.x += fmaxf(v0.x, 0.f);
        acc.y += fmaxf(v0.y, 0.f);
        acc.z += fmaxf(v0.z, 0.f);
        acc.w += fmaxf(v0.w, 0.f);
    }
    float sc = g_invcnt[w];
    agg[w * 32 + lane] = make_float4(acc.x * sc, acc.y * sc, acc.z * sc, acc.w * sc);
}

// ---------------- fused linear: out = agg@Wl^T + b + h@Wr^T (+relu) -----------
// Virtual X2 = [agg | h] (256-deep). k-tile BK=32 never straddles the 128
// boundary, so the source (agg vs h, Wl vs Wr) is a UNIFORM pointer per tile.
// Block tile 64 rows x BN cols, 256 threads, 4x(BN/16) register micro-tile.
template <int BN, bool RELU>
__global__ __launch_bounds__(256) void k_gemm(
    const float* __restrict__ xext,
    const float* __restrict__ Wl, const float* __restrict__ Wr,
    const float* __restrict__ bias,
    float* __restrict__ dout_ext, int which_in, int which_out, int dout)
{
    __shared__ float Ws[32 * (BN + 1)];   // [BK=32][BN+1] (pad: conflict-free T-store)
    __shared__ float Xs[64 * 36];         // [64][32 padded to 36] (16B-aligned rows)

    const float* hin = pick_in(which_in, xext);
    float* out = pick_out(which_out, dout_ext);

    const int tid = threadIdx.x;
    const int r0 = blockIdx.x * 64;
    const int CPT = BN / 16;
    const int tx = tid & 15;
    const int ty = tid >> 4;  // 0..15, each owns 4 rows

    float acc[4][CPT];
#pragma unroll
    for (int i = 0; i < 4; i++)
#pragma unroll
        for (int c = 0; c < CPT; c++) acc[i][c] = 0.f;

    for (int kt = 0; kt < 256; kt += 32) {
        const bool firstHalf = (kt < 128);
        const float* Wsrc = firstHalf ? Wl : Wr;       // [dout][128] row-major
        const float* Xsrc = firstHalf ? g_agg : hin;   // [N][128] row-major
        const int kb = kt & 127;

        // weight tile: coalesced along k, transposed store into Ws[kk][j]
        for (int i = tid; i < BN * 32; i += 256) {
            int j = i >> 5, kk = i & 31;
            float v = (j < dout) ? Wsrc[j * DIM + kb + kk] : 0.f;
            Ws[kk * (BN + 1) + j] = v;
        }
        // X tile: float4 loads (rows 16B-aligned), 512 float4s / 256 threads
        for (int i = tid; i < 64 * 8; i += 256) {
            int r = i >> 3, q = i & 7;
            int n = r0 + r;
            float4 v = make_float4(0.f, 0.f, 0.f, 0.f);
            if (n < N_NODES)
                v = *(const float4*)(Xsrc + n * DIM + kb + q * 4);
            *(float4*)(&Xs[r * 36 + q * 4]) = v;
        }
        __syncthreads();

#pragma unroll
        for (int kk = 0; kk < 32; kk++) {
            float w[CPT];
#pragma unroll
            for (int c = 0; c < CPT; c++) w[c] = Ws[kk * (BN + 1) + tx + c * 16];
#pragma unroll
            for (int i = 0; i < 4; i++) {
                float xv = Xs[(ty * 4 + i) * 36 + kk];
#pragma unroll
                for (int c = 0; c < CPT; c++) acc[i][c] = fmaf(xv, w[c], acc[i][c]);
            }
        }
        __syncthreads();
    }

    // bias into registers once, then store
    float bv[CPT];
#pragma unroll
    for (int c = 0; c < CPT; c++) {
        int j = tx + c * 16;
        bv[c] = (j < dout) ? bias[j] : 0.f;
    }
#pragma unroll
    for (int i = 0; i < 4; i++) {
        int n = r0 + ty * 4 + i;
        if (n < N_NODES) {
#pragma unroll
            for (int c = 0; c < CPT; c++) {
                int j = tx + c * 16;
                if (j < dout) {
                    float v = acc[i][c] + bv[c];
                    if (RELU) v = fmaxf(v, 0.f);
                    out[n * dout + j] = v;
                }
            }
        }
    }
}

// ---------------- global mean pool (batch is INT32) ----------------
__global__ void k_pool(const float* __restrict__ h3, const int* __restrict__ batch) {
    int i = blockIdx.x * blockDim.x + threadIdx.x;
    if (i < N_NODES * N_CLASSES) {
        int n = i / N_CLASSES;
        int c = i - n * N_CLASSES;
        int b = batch[n];
        if ((unsigned)b < (unsigned)N_GRAPHS)
            atomicAdd(&g_gsum[b * N_CLASSES + c], h3[i]);
    }
}
__global__ void k_gcnt(const int* __restrict__ batch) {
    int n = blockIdx.x * blockDim.x + threadIdx.x;
    if (n < N_NODES) {
        int b = batch[n];
        if ((unsigned)b < (unsigned)N_GRAPHS) atomicAdd(&g_gcnt[b], 1.f);
    }
}
__global__ void k_gfin(float* __restrict__ gout) {
    int i = blockIdx.x * blockDim.x + threadIdx.x;
    if (i < N_GRAPHS * N_CLASSES)
        gout[i] = g_gsum[i] / fmaxf(g_gcnt[i / N_CLASSES], 1.f);
}

// ---------------- launch: ONLY kernel launches ----------------
extern "C" void kernel_launch(void* const* d_in, const int* in_sizes, int n_in,
                              void* d_out, int out_size)
{
    const float* x     = (const float*)d_in[0];
    const int*   ei    = (const int*)d_in[1];     // int32: jax default (x64 off)
    const int*   batch = (const int*)d_in[2];     // int32
    const float* Wl0 = (const float*)d_in[3];
    const float* bl0 = (const float*)d_in[4];
    const float* Wr0 = (const float*)d_in[5];
    const float* Wl1 = (const float*)d_in[6];
    const float* bl1 = (const float*)d_in[7];
    const float* Wr1 = (const float*)d_in[8];
    const float* Wl2 = (const float*)d_in[9];
    const float* bl2 = (const float*)d_in[10];
    const float* Wr2 = (const float*)d_in[11];

    const int E = in_sizes[1] / 2;

    float* out  = (float*)d_out;
    float* hout = out;                           // [50000, 40]
    float* gout = out + N_NODES * N_CLASSES;     // [128, 40]

    const int TB = 256;
    // CSR build (edge_index constant within a call)
    k_zero<<<(N_NODES + TB - 1) / TB, TB>>>();
    k_count<<<(E + TB - 1) / TB, TB>>>(ei, E);
    k_scan<<<1, 1024>>>(E);
    k_fill<<<(E + TB - 1) / TB, TB>>>(ei, E);

    const int aggBlocks  = (N_NODES * 32 + TB - 1) / TB;   // one warp per node
    const int gemmBlocks = (N_NODES + 63) / 64;

    // layer 0: in = x, out = g_h1
    k_agg<<<aggBlocks, TB>>>(x, 0);
    k_gemm<128, true><<<gemmBlocks, TB>>>(x, Wl0, Wr0, bl0, hout, 0, 1, 128);
    // layer 1: in = g_h1, out = g_h2
    k_agg<<<aggBlocks, TB>>>(x, 1);
    k_gemm<128, true><<<gemmBlocks, TB>>>(x, Wl1, Wr1, bl1, hout, 1, 2, 128);
    // layer 2: in = g_h2, out = hout (d_out), no relu, dout = 40
    k_agg<<<aggBlocks, TB>>>(x, 2);
    k_gemm<64, false><<<gemmBlocks, TB>>>(x, Wl2, Wr2, bl2, hout, 2, 0, N_CLASSES);

    // global mean pool
    k_pool<<<(N_NODES * N_CLASSES + TB - 1) / TB, TB>>>(hout, batch);
    k_gcnt<<<(N_NODES + TB - 1) / TB, TB>>>(batch);
    k_gfin<<<(N_GRAPHS * N_CLASSES + TB - 1) / TB, TB>>>(gout);
}

// round 9
// speedup vs baseline: 1.0202x; 1.0202x over previous
#include <cuda_runtime.h>

#define N_NODES   50000
#define MAX_EDGES 600000
#define DIM       128
#define N_CLASSES 40
#define N_GRAPHS  128

// ---------------- static device scratch (16B-aligned: float4 traffic) ---------
__device__ __align__(16) float g_agg[N_NODES * DIM];
__device__ __align__(16) float g_h1[N_NODES * DIM];
__device__ __align__(16) float g_h2[N_NODES * DIM];
__device__ int   g_deg[N_NODES];
__device__ int   g_rowoff[N_NODES + 1];
__device__ int   g_cursor[N_NODES];
__device__ int   g_csrsrc[MAX_EDGES];
__device__ float g_invcnt[N_NODES];
__device__ float g_gsum[N_GRAPHS * N_CLASSES];
__device__ float g_gcnt[N_GRAPHS];

// device-side buffer selector: 0 = external ptr (param), 1 = g_h1, 2 = g_h2
__device__ __forceinline__ const float* pick_in(int w, const float* x) {
    if (w == 1) return g_h1;
    if (w == 2) return g_h2;
    return x;
}
__device__ __forceinline__ float* pick_out(int w, float* dout) {
    if (w == 1) return g_h1;
    if (w == 2) return g_h2;
    return dout;
}

// ---------------- zero per-call scratch ----------------
__global__ void k_zero() {
    int i = blockIdx.x * blockDim.x + threadIdx.x;
    if (i < N_NODES) g_deg[i] = 0;
    if (i < N_GRAPHS * N_CLASSES) g_gsum[i] = 0.f;
    if (i < N_GRAPHS) g_gcnt[i] = 0.f;
}

// ---------------- degree count (edge_index is INT32) ----------------
__global__ void k_count(const int* __restrict__ ei, int E) {
    int e = blockIdx.x * blockDim.x + threadIdx.x;
    if (e < E) {
        int d = ei[E + e];
        if ((unsigned)d < (unsigned)N_NODES) atomicAdd(&g_deg[d], 1);
    }
}

// ---------------- single-block exclusive scan over degrees ----------------
__global__ void k_scan(int E) {
    __shared__ int sums[1024];
    const int tid = threadIdx.x;
    const int CH = (N_NODES + 1023) / 1024;  // 49
    const int base = tid * CH;
    int s = 0;
    for (int i = 0; i < CH; i++) {
        int idx = base + i;
        if (idx < N_NODES) s += g_deg[idx];
    }
    sums[tid] = s;
    __syncthreads();
    for (int off = 1; off < 1024; off <<= 1) {
        int v = 0;
        if (tid >= off) v = sums[tid - off];
        __syncthreads();
        sums[tid] += v;
        __syncthreads();
    }
    int run = (tid == 0) ? 0 : sums[tid - 1];
    for (int i = 0; i < CH; i++) {
        int idx = base + i;
        if (idx < N_NODES) {
            g_rowoff[idx] = run;
            g_cursor[idx] = run;
            int d = g_deg[idx];
            run += d;
            g_invcnt[idx] = 1.0f / (float)max(d, 1);
        }
    }
    if (tid == 0) g_rowoff[N_NODES] = E;
}

// ---------------- fill CSR (src lists grouped by dst) ----------------
__global__ void k_fill(const int* __restrict__ ei, int E) {
    int e = blockIdx.x * blockDim.x + threadIdx.x;
    if (e < E) {
        int s = ei[e];
        int d = ei[E + e];
        if ((unsigned)s < (unsigned)N_NODES && (unsigned)d < (unsigned)N_NODES) {
            int p = atomicAdd(&g_cursor[d], 1);
            g_csrsrc[p] = s;
        }
    }
}

// ---------------- aggregation: g_agg[n] = mean over in-edges of relu(h[src]) --
__global__ void k_agg(const float* __restrict__ xext, int which_in) {
    const float4* hin = (const float4*)pick_in(which_in, xext);
    float4* agg = (float4*)g_agg;
    const int* __restrict__ rowoff = g_rowoff;
    const int* __restrict__ csrsrc = g_csrsrc;
    int w = (blockIdx.x * blockDim.x + threadIdx.x) >> 5;
    int lane = threadIdx.x & 31;
    if (w >= N_NODES) return;
    int beg = rowoff[w];
    int end = rowoff[w + 1];
    float4 acc = make_float4(0.f, 0.f, 0.f, 0.f);
    int e = beg;
    for (; e + 1 < end; e += 2) {
        int s0 = csrsrc[e];
        int s1 = csrsrc[e + 1];
        float4 v0 = hin[s0 * 32 + lane];
        float4 v1 = hin[s1 * 32 + lane];
        acc.x += fmaxf(v0.x, 0.f) + fmaxf(v1.x, 0.f);
        acc.y += fmaxf(v0.y, 0.f) + fmaxf(v1.y, 0.f);
        acc.z += fmaxf(v0.z, 0.f) + fmaxf(v1.z, 0.f);
        acc.w += fmaxf(v0.w, 0.f) + fmaxf(v1.w, 0.f);
    }
    if (e < end) {
        int s0 = csrsrc[e];
        float4 v0 = hin[s0 * 32 + lane];
        acc.x += fmaxf(v0.x, 0.f);
        acc.y += fmaxf(v0.y, 0.f);
        acc.z += fmaxf(v0.z, 0.f);
        acc.w += fmaxf(v0.w, 0.f);
    }
    float sc = g_invcnt[w];
    agg[w * 32 + lane] = make_float4(acc.x * sc, acc.y * sc, acc.z * sc, acc.w * sc);
}

// ---------------- fused linear: out = agg@Wl^T + b + h@Wr^T (+relu) -----------
// Virtual X2 = [agg | h] (256-deep); BK=32 tiles never straddle the 128
// boundary -> uniform source pointer per tile.
// Block tile: 128 rows x BN cols, 256 threads (16x16), 8x(BN/16) micro-tile.
// X tile stored k-major transposed (XsT[kk][row], stride 132) so the 8 row
// operands are two aligned float4 LDS (2 distinct addrs/warp -> broadcast).
// Weight reads: j = tx + 16c -> 16 banks, 2-way broadcast, conflict-free.
template <int BN, bool RELU>
__global__ __launch_bounds__(256, 2) void k_gemm(
    const float* __restrict__ xext,
    const float* __restrict__ Wl, const float* __restrict__ Wr,
    const float* __restrict__ bias,
    float* __restrict__ dout_ext, int which_in, int which_out, int dout)
{
    __shared__ float Ws[32 * (BN + 1)];   // [kk][j], stride BN+1 (odd): cf stores
    __shared__ float XsT[32 * 132];       // [kk][row], stride 132 (16B-aligned rows)

    const float* hin = pick_in(which_in, xext);
    float* out = pick_out(which_out, dout_ext);

    const int tid = threadIdx.x;
    const int r0 = blockIdx.x * 128;
    const int CPT = BN / 16;
    const int tx = tid & 15;
    const int ty = tid >> 4;          // 0..15, each owns 8 contiguous rows
    const int row0 = ty * 8;

    float acc[8][CPT];
#pragma unroll
    for (int i = 0; i < 8; i++)
#pragma unroll
        for (int c = 0; c < CPT; c++) acc[i][c] = 0.f;

    for (int kt = 0; kt < 256; kt += 32) {
        const bool firstHalf = (kt < 128);
        const float* Wsrc = firstHalf ? Wl : Wr;       // [dout][128] row-major
        const float* Xsrc = firstHalf ? g_agg : hin;   // [N][128] row-major
        const int kb = kt & 127;

        // weight tile: coalesced along k, transposed store Ws[kk][j]
        for (int i = tid; i < BN * 32; i += 256) {
            int j = i >> 5, kk = i & 31;
            float v = (j < dout) ? Wsrc[j * DIM + kb + kk] : 0.f;
            Ws[kk * (BN + 1) + j] = v;
        }
        // X tile: float4 global loads, transposed scalar stores XsT[kk][row]
        for (int i = tid; i < 128 * 8; i += 256) {
            int r = i >> 3, q = i & 7;
            int n = r0 + r;
            float4 v = make_float4(0.f, 0.f, 0.f, 0.f);
            if (n < N_NODES)
                v = *(const float4*)(Xsrc + n * DIM + kb + q * 4);
            XsT[(q * 4 + 0) * 132 + r] = v.x;
            XsT[(q * 4 + 1) * 132 + r] = v.y;
            XsT[(q * 4 + 2) * 132 + r] = v.z;
            XsT[(q * 4 + 3) * 132 + r] = v.w;
        }
        __syncthreads();

#pragma unroll 8
        for (int kk = 0; kk < 32; kk++) {
            float w[CPT];
#pragma unroll
            for (int c = 0; c < CPT; c++) w[c] = Ws[kk * (BN + 1) + tx + c * 16];
            float4 xa = *(const float4*)(&XsT[kk * 132 + row0]);
            float4 xb = *(const float4*)(&XsT[kk * 132 + row0 + 4]);
            float xv[8] = {xa.x, xa.y, xa.z, xa.w, xb.x, xb.y, xb.z, xb.w};
#pragma unroll
            for (int i = 0; i < 8; i++)
#pragma unroll
                for (int c = 0; c < CPT; c++)
                    acc[i][c] = fmaf(xv[i], w[c], acc[i][c]);
        }
        __syncthreads();
    }

    // bias into registers once, then store
    float bv[CPT];
#pragma unroll
    for (int c = 0; c < CPT; c++) {
        int j = tx + c * 16;
        bv[c] = (j < dout) ? bias[j] : 0.f;
    }
#pragma unroll
    for (int i = 0; i < 8; i++) {
        int n = r0 + row0 + i;
        if (n < N_NODES) {
#pragma unroll
            for (int c = 0; c < CPT; c++) {
                int j = tx + c * 16;
                if (j < dout) {
                    float v = acc[i][c] + bv[c];
                    if (RELU) v = fmaxf(v, 0.f);
                    out[n * dout + j] = v;
                }
            }
        }
    }
}

// ---------------- global mean pool (batch is INT32) ----------------
__global__ void k_pool(const float* __restrict__ h3, const int* __restrict__ batch) {
    int i = blockIdx.x * blockDim.x + threadIdx.x;
    if (i < N_NODES * N_CLASSES) {
        int n = i / N_CLASSES;
        int c = i - n * N_CLASSES;
        int b = batch[n];
        if ((unsigned)b < (unsigned)N_GRAPHS)
            atomicAdd(&g_gsum[b * N_CLASSES + c], h3[i]);
    }
}
__global__ void k_gcnt(const int* __restrict__ batch) {
    int n = blockIdx.x * blockDim.x + threadIdx.x;
    if (n < N_NODES) {
        int b = batch[n];
        if ((unsigned)b < (unsigned)N_GRAPHS) atomicAdd(&g_gcnt[b], 1.f);
    }
}
__global__ void k_gfin(float* __restrict__ gout) {
    int i = blockIdx.x * blockDim.x + threadIdx.x;
    if (i < N_GRAPHS * N_CLASSES)
        gout[i] = g_gsum[i] / fmaxf(g_gcnt[i / N_CLASSES], 1.f);
}

// ---------------- launch: ONLY kernel launches ----------------
extern "C" void kernel_launch(void* const* d_in, const int* in_sizes, int n_in,
                              void* d_out, int out_size)
{
    const float* x     = (const float*)d_in[0];
    const int*   ei    = (const int*)d_in[1];     // int32 (jax x64 disabled)
    const int*   batch = (const int*)d_in[2];     // int32
    const float* Wl0 = (const float*)d_in[3];
    const float* bl0 = (const float*)d_in[4];
    const float* Wr0 = (const float*)d_in[5];
    const float* Wl1 = (const float*)d_in[6];
    const float* bl1 = (const float*)d_in[7];
    const float* Wr1 = (const float*)d_in[8];
    const float* Wl2 = (const float*)d_in[9];
    const float* bl2 = (const float*)d_in[10];
    const float* Wr2 = (const float*)d_in[11];

    const int E = in_sizes[1] / 2;

    float* out  = (float*)d_out;
    float* hout = out;                           // [50000, 40]
    float* gout = out + N_NODES * N_CLASSES;     // [128, 40]

    const int TB = 256;
    // CSR build (edge_index constant within a call)
    k_zero<<<(N_NODES + TB - 1) / TB, TB>>>();
    k_count<<<(E + TB - 1) / TB, TB>>>(ei, E);
    k_scan<<<1, 1024>>>(E);
    k_fill<<<(E + TB - 1) / TB, TB>>>(ei, E);

    const int aggBlocks  = (N_NODES * 32 + TB - 1) / TB;   // one warp per node
    const int gemmBlocks = (N_NODES + 127) / 128;          // 128-row tiles

    // layer 0: in = x, out = g_h1
    k_agg<<<aggBlocks, TB>>>(x, 0);
    k_gemm<128, true><<<gemmBlocks, TB>>>(x, Wl0, Wr0, bl0, hout, 0, 1, 128);
    // layer 1: in = g_h1, out = g_h2
    k_agg<<<aggBlocks, TB>>>(x, 1);
    k_gemm<128, true><<<gemmBlocks, TB>>>(x, Wl1, Wr1, bl1, hout, 1, 2, 128);
    // layer 2: in = g_h2, out = hout (d_out), no relu, dout = 40
    k_agg<<<aggBlocks, TB>>>(x, 2);
    k_gemm<64, false><<<gemmBlocks, TB>>>(x, Wl2, Wr2, bl2, hout, 2, 0, N_CLASSES);

    // global mean pool
    k_pool<<<(N_NODES * N_CLASSES + TB - 1) / TB, TB>>>(hout, batch);
    k_gcnt<<<(N_NODES + TB - 1) / TB, TB>>>(batch);
    k_gfin<<<(N_GRAPHS * N_CLASSES + TB - 1) / TB, TB>>>(gout);
}